// round 2
// baseline (speedup 1.0000x reference)
#include <cuda_runtime.h>
#include <cstdint>

// ---------------- problem constants ----------------
#define BATCH   65536
#define IN_F    1024
#define OUT_F   1024
#define BM      128
#define BN      128
#define BK      32
#define NK      (IN_F / BK)      // 32 k-chunks
#define STAGES  4

#define STAGE_BYTES 32768        // A 16KB + B 16KB
#define B_OFF       16384
#define SMEM_PAD    2048         // alignment slack + scratch header
#define SMEM_TOTAL  (SMEM_PAD + STAGES * STAGE_BYTES)   // 133120 (also covers 69.6KB epilogue)

// round-nearest tf32 copies of the inputs (cvt.rna) — avoids the systematic
// truncation bias of feeding raw fp32 bits to the tf32 MMA.
__device__ float g_Xc[(size_t)BATCH * IN_F];   // 256 MB scratch
__device__ float g_Wc[(size_t)OUT_F * IN_F];   // 4 MB scratch

// ---------------- helpers ----------------
__device__ __forceinline__ uint32_t smem_u32(const void* p) {
    uint32_t a;
    asm("{ .reg .u64 t; cvta.to.shared.u64 t, %1; cvt.u32.u64 %0, t; }" : "=r"(a) : "l"(p));
    return a;
}
__device__ __forceinline__ void cp16(uint32_t s, const void* g) {
    asm volatile("cp.async.cg.shared.global [%0], [%1], 16;" :: "r"(s), "l"(g));
}
#define CP_COMMIT() asm volatile("cp.async.commit_group;" ::: "memory")
#define CP_WAIT(n)  asm volatile("cp.async.wait_group %0;" :: "n"(n) : "memory")

#define LDSM4(R, A) \
    asm volatile("ldmatrix.sync.aligned.m8n8.x4.shared.b16 {%0,%1,%2,%3}, [%4];" \
        : "=r"((R)[0]), "=r"((R)[1]), "=r"((R)[2]), "=r"((R)[3]) : "r"(A))

#define MMA_TF32(D, A, B) \
    asm volatile("mma.sync.aligned.m16n8k8.row.col.f32.tf32.tf32.f32 " \
        "{%0,%1,%2,%3}, {%4,%5,%6,%7}, {%8,%9}, {%0,%1,%2,%3};" \
        : "+f"((D)[0]), "+f"((D)[1]), "+f"((D)[2]), "+f"((D)[3]) \
        : "r"((A)[0]), "r"((A)[1]), "r"((A)[2]), "r"((A)[3]), "r"((B)[0]), "r"((B)[1]))

__device__ __forceinline__ float tanh_ap(float x) {
    float y; asm("tanh.approx.f32 %0, %1;" : "=f"(y) : "f"(x)); return y;
}
__device__ __forceinline__ float sin_ap(float x) {
    float y; asm("sin.approx.f32 %0, %1;" : "=f"(y) : "f"(x)); return y;
}

// ---------------- conversion kernels (fp32 -> tf32 round-nearest) ----------------
__global__ void __launch_bounds__(256) cvt_x_kernel(const float4* __restrict__ in) {
    size_t i = (size_t)blockIdx.x * 256 + threadIdx.x;
    float4 v = in[i];
    uint32_t r0, r1, r2, r3;
    asm("cvt.rna.tf32.f32 %0, %1;" : "=r"(r0) : "f"(v.x));
    asm("cvt.rna.tf32.f32 %0, %1;" : "=r"(r1) : "f"(v.y));
    asm("cvt.rna.tf32.f32 %0, %1;" : "=r"(r2) : "f"(v.z));
    asm("cvt.rna.tf32.f32 %0, %1;" : "=r"(r3) : "f"(v.w));
    float4 o = { __uint_as_float(r0), __uint_as_float(r1),
                 __uint_as_float(r2), __uint_as_float(r3) };
    ((float4*)g_Xc)[i] = o;
}
__global__ void __launch_bounds__(256) cvt_w_kernel(const float4* __restrict__ in) {
    size_t i = (size_t)blockIdx.x * 256 + threadIdx.x;
    float4 v = in[i];
    uint32_t r0, r1, r2, r3;
    asm("cvt.rna.tf32.f32 %0, %1;" : "=r"(r0) : "f"(v.x));
    asm("cvt.rna.tf32.f32 %0, %1;" : "=r"(r1) : "f"(v.y));
    asm("cvt.rna.tf32.f32 %0, %1;" : "=r"(r2) : "f"(v.z));
    asm("cvt.rna.tf32.f32 %0, %1;" : "=r"(r3) : "f"(v.w));
    float4 o = { __uint_as_float(r0), __uint_as_float(r1),
                 __uint_as_float(r2), __uint_as_float(r3) };
    ((float4*)g_Wc)[i] = o;
}

// ---------------- fused tf32 GEMM + cyclic activations ----------------
__global__ void __launch_bounds__(256, 1)
gemm_act_kernel(const float* __restrict__ Bv, float* __restrict__ O) {
    extern __shared__ char smem[];
    const uint32_t sb = smem_u32(smem);
    const uint32_t sT = (sb + 127) & ~127u;       // 128B-aligned tile base
    const uint32_t tiles = sT + SMEM_PAD - 128;   // keep inside allocation

    const int tid = threadIdx.x;
    const int wid = tid >> 5;
    const int lane = tid & 31;
    const int warp_m = wid & 3;       // 0..3 -> m offset *32
    const int warp_n = wid >> 2;      // 0..1 -> n offset *64

    const int nt = blockIdx.x & 7;            // 8 N-tiles; consecutive bids share A tile in L2
    const int mt = blockIdx.x >> 3;           // 512 M-tiles
    const int m0 = mt * BM;
    const int n0 = nt * BN;

    // ---- producer per-thread addressing (all 256 threads) ----
    const int rr = tid >> 3;                  // row 0..31 (+32*i)
    const int cc = tid & 7;                   // 16B vec col
    const uint32_t sw_off = (uint32_t)(rr * 128 + ((cc * 16) ^ ((rr & 7) << 4)));
    const float* gAt = g_Xc + (size_t)(m0 + rr) * IN_F + cc * 4;
    const float* gBt = g_Wc + (size_t)(n0 + rr) * IN_F + cc * 4;

    // ---- consumer (ldmatrix) per-thread base offsets within a stage ----
    // A: rows warp_m*32 + (lane&15), kbyte (lane>>4)*16
    const int arow = warp_m * 32 + (lane & 15);
    const uint32_t offA = (uint32_t)(arow * 128 + (((lane >> 4) * 16) ^ ((arow & 7) << 4)));
    // B: rows warp_n*64 + (lane&7) + ((lane>>4)?8:0), kbyte ((lane>>3)&1)*16
    const int brow = warp_n * 64 + (lane & 7) + ((lane >> 4) << 3);
    const uint32_t offB = (uint32_t)(brow * 128 + ((((lane >> 3) & 1) * 16) ^ ((brow & 7) << 4)))
                        + B_OFF;

    float acc[2][8][4];
    #pragma unroll
    for (int a = 0; a < 2; ++a)
        #pragma unroll
        for (int f = 0; f < 8; ++f)
            #pragma unroll
            for (int c = 0; c < 4; ++c) acc[a][f][c] = 0.0f;

    // ---- prologue: stages 0..2 ----
    #pragma unroll
    for (int s = 0; s < 3; ++s) {
        const uint32_t base = tiles + s * STAGE_BYTES + sw_off;
        const float* a = gAt + s * BK;
        const float* b = gBt + s * BK;
        #pragma unroll
        for (int i = 0; i < 4; ++i) {
            cp16(base + i * 4096,         a + (size_t)i * 32 * IN_F);
            cp16(base + B_OFF + i * 4096, b + (size_t)i * 32 * IN_F);
        }
        CP_COMMIT();
    }

    // ---- mainloop ----
    for (int kc = 0; kc < NK; ++kc) {
        CP_WAIT(2);
        __syncthreads();

        // issue stage kc+3 (its buffer was freed by the barrier above)
        if (kc + 3 < NK) {
            const int s = (kc + 3) & 3;
            const uint32_t base = tiles + s * STAGE_BYTES + sw_off;
            const float* a = gAt + (kc + 3) * BK;
            const float* b = gBt + (kc + 3) * BK;
            #pragma unroll
            for (int i = 0; i < 4; ++i) {
                cp16(base + i * 4096,         a + (size_t)i * 32 * IN_F);
                cp16(base + B_OFF + i * 4096, b + (size_t)i * 32 * IN_F);
            }
        }
        CP_COMMIT();   // always commit (empty groups keep the wait-count invariant)

        const uint32_t stg = tiles + (kc & 3) * STAGE_BYTES;
        const uint32_t aB = stg + offA;
        const uint32_t bB = stg + offB;
        #pragma unroll
        for (int j = 0; j < 4; ++j) {
            const uint32_t jx = (uint32_t)(j << 5);
            uint32_t a0[4], a1[4], b[16];
            LDSM4(a0, aB ^ jx);
            LDSM4(a1, (aB + 2048) ^ jx);
            LDSM4(&b[0],  bB ^ jx);
            LDSM4(&b[4],  (bB + 2048) ^ jx);
            LDSM4(&b[8],  (bB + 4096) ^ jx);
            LDSM4(&b[12], (bB + 6144) ^ jx);
            #pragma unroll
            for (int f = 0; f < 8; ++f) {
                MMA_TF32(acc[0][f], a0, &b[2 * f]);
                MMA_TF32(acc[1][f], a1, &b[2 * f]);
            }
        }
    }

    // ---- epilogue: bias + cyclic activations, staged through smem ----
    CP_WAIT(0);
    __syncthreads();    // everyone done reading tiles; reuse smem as output staging

    float bs0[8], bs1[8];
    #pragma unroll
    for (int f = 0; f < 8; ++f) {
        const int cb = n0 + warp_n * 64 + f * 8 + 2 * (lane & 3);
        bs0[f] = __ldg(Bv + cb);
        bs1[f] = __ldg(Bv + cb + 1);
    }

    float* eb = (float*)(smem + (tiles - sb));    // stride-136 staging buffer
    const bool even = (lane & 1) == 0;            // cols 0,2 mod 4 vs 1,3 mod 4

    #pragma unroll
    for (int mf = 0; mf < 2; ++mf) {
        #pragma unroll
        for (int h = 0; h < 2; ++h) {
            const int row = warp_m * 32 + mf * 16 + (lane >> 2) + h * 8;
            #pragma unroll
            for (int f = 0; f < 8; ++f) {
                float v0 = acc[mf][f][2 * h]     + bs0[f];
                float v1 = acc[mf][f][2 * h + 1] + bs1[f];
                // c0 col%4 in {0,2}: tanh (even lane) / relu (odd lane)
                float t0 = tanh_ap(v0);
                float r0 = fmaxf(v0, 0.0f);
                float o0 = even ? t0 : r0;
                // c1 col%4 in {1,3}: sin (even lane) / sigmoid (odd lane)
                float s1 = sin_ap(v1);
                float g1 = fmaf(0.5f, tanh_ap(0.5f * v1), 0.5f);
                float o1 = even ? s1 : g1;
                float2 o = { o0, o1 };
                *(float2*)&eb[(size_t)row * 136 + warp_n * 64 + f * 8 + 2 * (lane & 3)] = o;
            }
        }
    }
    __syncthreads();

    // coalesced 128B streaming stores
    #pragma unroll
    for (int i = 0; i < 16; ++i) {
        const int idx = tid + i * 256;
        const int row = idx >> 5;
        const int c4  = idx & 31;
        float4 v = *(const float4*)&eb[(size_t)row * 136 + c4 * 4];
        *(float4*)(O + (size_t)(m0 + row) * OUT_F + n0 + c4 * 4) = v;
    }
}

// ---------------- launch ----------------
extern "C" void kernel_launch(void* const* d_in, const int* in_sizes, int n_in,
                              void* d_out, int out_size) {
    const float* X  = (const float*)d_in[0];
    const float* Wt = (const float*)d_in[1];
    const float* Bv = (const float*)d_in[2];
    float* O = (float*)d_out;

    cvt_x_kernel<<<(int)(((size_t)BATCH * IN_F / 4) / 256), 256>>>((const float4*)X);
    cvt_w_kernel<<<(int)(((size_t)OUT_F * IN_F / 4) / 256), 256>>>((const float4*)Wt);

    cudaFuncSetAttribute(gemm_act_kernel,
                         cudaFuncAttributeMaxDynamicSharedMemorySize, SMEM_TOTAL);
    gemm_act_kernel<<<(BATCH / BM) * (OUT_F / BN), 256, SMEM_TOTAL>>>(Bv, O);
}

// round 3
// speedup vs baseline: 1.1721x; 1.1721x over previous
#include <cuda_runtime.h>
#include <cstdint>

// ---------------- problem constants ----------------
#define BATCH   65536
#define IN_F    1024
#define OUT_F   1024
#define BM      256
#define BN      128
#define BK      32
#define NK      (IN_F / BK)      // 32 k-chunks
#define NTHREADS 512

#define STAGE_BYTES 49152        // A 32KB + B 16KB
#define B_OFF       32768
#define SMEM_PAD    2048
#define SMEM_TOTAL  (SMEM_PAD + 4 * STAGE_BYTES)   // 198656

// round-nearest tf32 copy of W only (4 MB). X is converted in-register.
__device__ float g_Wc[(size_t)OUT_F * IN_F];

// ---------------- helpers ----------------
__device__ __forceinline__ uint32_t smem_u32(const void* p) {
    uint32_t a;
    asm("{ .reg .u64 t; cvta.to.shared.u64 t, %1; cvt.u32.u64 %0, t; }" : "=r"(a) : "l"(p));
    return a;
}
__device__ __forceinline__ void cp16(uint32_t s, const void* g) {
    asm volatile("cp.async.cg.shared.global [%0], [%1], 16;" :: "r"(s), "l"(g));
}
#define CP_COMMIT() asm volatile("cp.async.commit_group;" ::: "memory")
#define CP_WAIT(n)  asm volatile("cp.async.wait_group %0;" :: "n"(n) : "memory")

#define LDSM4(R, A) \
    asm volatile("ldmatrix.sync.aligned.m8n8.x4.shared.b16 {%0,%1,%2,%3}, [%4];" \
        : "=r"((R)[0]), "=r"((R)[1]), "=r"((R)[2]), "=r"((R)[3]) : "r"(A))

#define MMA_TF32(D, A, B) \
    asm volatile("mma.sync.aligned.m16n8k8.row.col.f32.tf32.tf32.f32 " \
        "{%0,%1,%2,%3}, {%4,%5,%6,%7}, {%8,%9}, {%0,%1,%2,%3};" \
        : "+f"((D)[0]), "+f"((D)[1]), "+f"((D)[2]), "+f"((D)[3]) \
        : "r"((A)[0]), "r"((A)[1]), "r"((A)[2]), "r"((A)[3]), "r"((B)[0]), "r"((B)[1]))

__device__ __forceinline__ uint32_t rna_tf32(uint32_t bits) {
    uint32_t r;
    asm("cvt.rna.tf32.f32 %0, %1;" : "=r"(r) : "f"(__uint_as_float(bits)));
    return r;
}
__device__ __forceinline__ float tanh_ap(float x) {
    float y; asm("tanh.approx.f32 %0, %1;" : "=f"(y) : "f"(x)); return y;
}
__device__ __forceinline__ float sin_ap(float x) {
    float y; asm("sin.approx.f32 %0, %1;" : "=f"(y) : "f"(x)); return y;
}

// ---------------- W conversion (fp32 -> tf32 round-nearest) ----------------
__global__ void __launch_bounds__(256) cvt_w_kernel(const float4* __restrict__ in) {
    size_t i = (size_t)blockIdx.x * 256 + threadIdx.x;
    float4 v = in[i];
    uint32_t r0, r1, r2, r3;
    asm("cvt.rna.tf32.f32 %0, %1;" : "=r"(r0) : "f"(v.x));
    asm("cvt.rna.tf32.f32 %0, %1;" : "=r"(r1) : "f"(v.y));
    asm("cvt.rna.tf32.f32 %0, %1;" : "=r"(r2) : "f"(v.z));
    asm("cvt.rna.tf32.f32 %0, %1;" : "=r"(r3) : "f"(v.w));
    float4 o = { __uint_as_float(r0), __uint_as_float(r1),
                 __uint_as_float(r2), __uint_as_float(r3) };
    ((float4*)g_Wc)[i] = o;
}

// ---------------- fused tf32 GEMM + cyclic activations ----------------
__global__ void __launch_bounds__(NTHREADS, 1)
gemm_act_kernel(const float* __restrict__ X, const float* __restrict__ Bv,
                float* __restrict__ O) {
    extern __shared__ char smem[];
    const uint32_t sb = smem_u32(smem);
    const uint32_t tiles = ((sb + 127) & ~127u) + SMEM_PAD - 128;

    const int tid = threadIdx.x;
    const int wid = tid >> 5;
    const int lane = tid & 31;
    const int warp_m = wid & 7;       // 0..7 -> m offset *32
    const int warp_n = wid >> 3;      // 0..1 -> n offset *64

    const int nt = blockIdx.x & 7;    // 8 N-tiles; consecutive bids share A tile in L2
    const int mt = blockIdx.x >> 3;   // 256 M-tiles
    const int m0 = mt * BM;
    const int n0 = nt * BN;

    // ---- producer per-thread addressing (512 threads) ----
    const int rr = tid >> 3;                  // 0..63
    const int cc = tid & 7;                   // 16B vec col
    const uint32_t sw_base = (uint32_t)((cc * 16) ^ ((rr & 7) << 4));
    const float* gAt = X    + (size_t)(m0 + rr) * IN_F + cc * 4;
    const float* gBt = g_Wc + (size_t)(n0 + rr) * IN_F + cc * 4;

    // ---- consumer (ldmatrix) per-thread base offsets within a stage ----
    const int arow = warp_m * 32 + (lane & 15);
    const uint32_t offA = (uint32_t)(arow * 128 + (((lane >> 4) * 16) ^ ((arow & 7) << 4)));
    const int brow = warp_n * 64 + (lane & 7) + ((lane >> 4) << 3);
    const uint32_t offB = (uint32_t)(brow * 128 + ((((lane >> 3) & 1) * 16) ^ ((brow & 7) << 4)))
                        + B_OFF;

    float acc[2][8][4];
    #pragma unroll
    for (int a = 0; a < 2; ++a)
        #pragma unroll
        for (int f = 0; f < 8; ++f)
            #pragma unroll
            for (int c = 0; c < 4; ++c) acc[a][f][c] = 0.0f;

    // ---- prologue: stages 0..2 ----
    #pragma unroll
    for (int s = 0; s < 3; ++s) {
        const uint32_t base = tiles + s * STAGE_BYTES + rr * 128 + sw_base;
        const float* a = gAt + s * BK;
        const float* b = gBt + s * BK;
        #pragma unroll
        for (int i = 0; i < 4; ++i)           // A: 4 x 64 rows
            cp16(base + i * 8192, a + (size_t)i * 64 * IN_F);
        #pragma unroll
        for (int i = 0; i < 2; ++i)           // B: 2 x 64 rows
            cp16(base + B_OFF + i * 8192, b + (size_t)i * 64 * IN_F);
        CP_COMMIT();
    }

    // ---- mainloop ----
    for (int kc = 0; kc < NK; ++kc) {
        CP_WAIT(2);
        __syncthreads();

        if (kc + 3 < NK) {
            const int s = (kc + 3) & 3;
            const uint32_t base = tiles + s * STAGE_BYTES + rr * 128 + sw_base;
            const float* a = gAt + (kc + 3) * BK;
            const float* b = gBt + (kc + 3) * BK;
            #pragma unroll
            for (int i = 0; i < 4; ++i)
                cp16(base + i * 8192, a + (size_t)i * 64 * IN_F);
            #pragma unroll
            for (int i = 0; i < 2; ++i)
                cp16(base + B_OFF + i * 8192, b + (size_t)i * 64 * IN_F);
        }
        CP_COMMIT();

        const uint32_t stg = tiles + (kc & 3) * STAGE_BYTES;
        const uint32_t aB = stg + offA;
        const uint32_t bB = stg + offB;
        #pragma unroll
        for (int j = 0; j < 4; ++j) {
            const uint32_t jx = (uint32_t)(j << 5);
            uint32_t a0[4], a1[4], b[16];
            LDSM4(a0, aB ^ jx);
            LDSM4(a1, (aB + 2048) ^ jx);
            LDSM4(&b[0],  bB ^ jx);
            LDSM4(&b[4],  (bB + 2048) ^ jx);
            LDSM4(&b[8],  (bB + 4096) ^ jx);
            LDSM4(&b[12], (bB + 6144) ^ jx);
            // round-nearest tf32 on A fragments (B comes pre-converted from g_Wc)
            #pragma unroll
            for (int q = 0; q < 4; ++q) { a0[q] = rna_tf32(a0[q]); a1[q] = rna_tf32(a1[q]); }
            #pragma unroll
            for (int f = 0; f < 8; ++f) {
                MMA_TF32(acc[0][f], a0, &b[2 * f]);
                MMA_TF32(acc[1][f], a1, &b[2 * f]);
            }
        }
    }

    // ---- epilogue: bias + cyclic activations, staged through smem ----
    CP_WAIT(0);
    __syncthreads();    // tiles no longer needed; reuse smem as output staging

    float bs0[8], bs1[8];
    #pragma unroll
    for (int f = 0; f < 8; ++f) {
        const int cb = n0 + warp_n * 64 + f * 8 + 2 * (lane & 3);
        bs0[f] = __ldg(Bv + cb);
        bs1[f] = __ldg(Bv + cb + 1);
    }

    float* eb = (float*)(smem + (tiles - sb));    // stride-136 staging, 256 rows
    const bool even = (lane & 1) == 0;

    #pragma unroll
    for (int mf = 0; mf < 2; ++mf) {
        #pragma unroll
        for (int h = 0; h < 2; ++h) {
            const int row = warp_m * 32 + mf * 16 + (lane >> 2) + h * 8;
            #pragma unroll
            for (int f = 0; f < 8; ++f) {
                float v0 = acc[mf][f][2 * h]     + bs0[f];
                float v1 = acc[mf][f][2 * h + 1] + bs1[f];
                float o0 = even ? tanh_ap(v0) : fmaxf(v0, 0.0f);            // col%4 0|2
                float o1 = even ? sin_ap(v1)
                                : fmaf(0.5f, tanh_ap(0.5f * v1), 0.5f);     // col%4 1|3
                float2 o = { o0, o1 };
                *(float2*)&eb[(size_t)row * 136 + warp_n * 64 + f * 8 + 2 * (lane & 3)] = o;
            }
        }
    }
    __syncthreads();

    // coalesced 128B streaming stores: 256 rows x 32 float4
    #pragma unroll
    for (int i = 0; i < 16; ++i) {
        const int idx = tid + i * NTHREADS;
        const int row = idx >> 5;
        const int c4  = idx & 31;
        float4 v = *(const float4*)&eb[(size_t)row * 136 + c4 * 4];
        *(float4*)(O + (size_t)(m0 + row) * OUT_F + n0 + c4 * 4) = v;
    }
}

// ---------------- launch ----------------
extern "C" void kernel_launch(void* const* d_in, const int* in_sizes, int n_in,
                              void* d_out, int out_size) {
    const float* X  = (const float*)d_in[0];
    const float* Wt = (const float*)d_in[1];
    const float* Bv = (const float*)d_in[2];
    float* O = (float*)d_out;

    cvt_w_kernel<<<(int)(((size_t)OUT_F * IN_F / 4) / 256), 256>>>((const float4*)Wt);

    cudaFuncSetAttribute(gemm_act_kernel,
                         cudaFuncAttributeMaxDynamicSharedMemorySize, SMEM_TOTAL);
    gemm_act_kernel<<<(BATCH / BM) * (OUT_F / BN), NTHREADS, SMEM_TOTAL>>>(X, Bv, O);
}

// round 5
// speedup vs baseline: 1.8866x; 1.6096x over previous
#include <cuda_runtime.h>
#include <cuda_fp16.h>
#include <cstdint>

// ---------------- problem constants ----------------
#define BATCH   65536
#define IN_F    1024
#define OUT_F   1024
#define BM      256
#define BN      128
#define BK      64
#define NK      (IN_F / BK)      // 16 k-chunks
#define NTHREADS 512

#define STAGE_BYTES 49152        // A 32KB (256x64 f16) + B 16KB (128x64 f16)
#define B_OFF       32768
#define SMEM_PAD    2048
#define SMEM_TOTAL  (SMEM_PAD + 4 * STAGE_BYTES)   // 198656

// fp16 copies (round-nearest). Same 10 mantissa bits as tf32; fp32 accumulate.
__device__ __half g_Xh[(size_t)BATCH * IN_F];   // 128 MB scratch
__device__ __half g_Wh[(size_t)OUT_F * IN_F];   // 2 MB scratch

// ---------------- helpers ----------------
__device__ __forceinline__ uint32_t h2_u32(__half2 h) {
    union { __half2 h; uint32_t u; } c; c.h = h; return c.u;
}
__device__ __forceinline__ uint32_t smem_u32(const void* p) {
    uint32_t a;
    asm("{ .reg .u64 t; cvta.to.shared.u64 t, %1; cvt.u32.u64 %0, t; }" : "=r"(a) : "l"(p));
    return a;
}
__device__ __forceinline__ void cp16(uint32_t s, const void* g) {
    asm volatile("cp.async.cg.shared.global [%0], [%1], 16;" :: "r"(s), "l"(g));
}
#define CP_COMMIT() asm volatile("cp.async.commit_group;" ::: "memory")
#define CP_WAIT(n)  asm volatile("cp.async.wait_group %0;" :: "n"(n) : "memory")

#define LDSM4(R, A) \
    asm volatile("ldmatrix.sync.aligned.m8n8.x4.shared.b16 {%0,%1,%2,%3}, [%4];" \
        : "=r"((R)[0]), "=r"((R)[1]), "=r"((R)[2]), "=r"((R)[3]) : "r"(A))

#define MMA_F16(D, A, B0, B1) \
    asm volatile("mma.sync.aligned.m16n8k16.row.col.f32.f16.f16.f32 " \
        "{%0,%1,%2,%3}, {%4,%5,%6,%7}, {%8,%9}, {%0,%1,%2,%3};" \
        : "+f"((D)[0]), "+f"((D)[1]), "+f"((D)[2]), "+f"((D)[3]) \
        : "r"((A)[0]), "r"((A)[1]), "r"((A)[2]), "r"((A)[3]), "r"(B0), "r"(B1))

__device__ __forceinline__ float tanh_ap(float x) {
    float y; asm("tanh.approx.f32 %0, %1;" : "=f"(y) : "f"(x)); return y;
}
__device__ __forceinline__ float sin_ap(float x) {
    float y; asm("sin.approx.f32 %0, %1;" : "=f"(y) : "f"(x)); return y;
}

// ---------------- conversion kernels (fp32 -> fp16 round-nearest) ----------------
__global__ void __launch_bounds__(256) cvt_x_kernel(const float4* __restrict__ in) {
    size_t i = (size_t)blockIdx.x * 256 + threadIdx.x;   // handles 8 floats
    float4 v0 = in[2 * i], v1 = in[2 * i + 1];
    uint4 o = { h2_u32(__floats2half2_rn(v0.x, v0.y)),
                h2_u32(__floats2half2_rn(v0.z, v0.w)),
                h2_u32(__floats2half2_rn(v1.x, v1.y)),
                h2_u32(__floats2half2_rn(v1.z, v1.w)) };
    ((uint4*)g_Xh)[i] = o;
}
__global__ void __launch_bounds__(256) cvt_w_kernel(const float4* __restrict__ in) {
    size_t i = (size_t)blockIdx.x * 256 + threadIdx.x;
    float4 v0 = in[2 * i], v1 = in[2 * i + 1];
    uint4 o = { h2_u32(__floats2half2_rn(v0.x, v0.y)),
                h2_u32(__floats2half2_rn(v0.z, v0.w)),
                h2_u32(__floats2half2_rn(v1.x, v1.y)),
                h2_u32(__floats2half2_rn(v1.z, v1.w)) };
    ((uint4*)g_Wh)[i] = o;
}

// ---------------- fused fp16 GEMM (fp32 accum) + cyclic activations ----------------
__global__ void __launch_bounds__(NTHREADS, 1)
gemm_act_kernel(const float* __restrict__ Bv, float* __restrict__ O) {
    extern __shared__ char smem[];
    const uint32_t sb = smem_u32(smem);
    const uint32_t tiles = ((sb + 127) & ~127u) + SMEM_PAD - 128;

    const int tid = threadIdx.x;
    const int wid = tid >> 5;
    const int lane = tid & 31;
    const int warp_m = wid & 7;       // 0..7 -> m offset *32
    const int warp_n = wid >> 3;      // 0..1 -> n offset *64

    const int nt = blockIdx.x & 7;    // 8 N-tiles; consecutive bids share A tile in L2
    const int mt = blockIdx.x >> 3;   // 256 M-tiles
    const int m0 = mt * BM;
    const int n0 = nt * BN;

    // ---- producer addressing: row = 128B of fp16 (64 halves) ----
    const int rr = tid >> 3;                  // 0..63
    const int cc = tid & 7;                   // 16B vec
    const uint32_t sw_base = (uint32_t)((cc * 16) ^ ((rr & 7) << 4));
    const __half* gAt = g_Xh + (size_t)(m0 + rr) * IN_F + cc * 8;
    const __half* gBt = g_Wh + (size_t)(n0 + rr) * IN_F + cc * 8;

    // ---- ldmatrix per-thread offsets ----
    // A (16x16 f16 fragment): lanes 0-15 -> m rows, lanes 16-31 -> same rows, k+8
    const int arow = warp_m * 32 + (lane & 15);
    const uint32_t offA = (uint32_t)(arow * 128 + (((lane >> 4) * 16) ^ ((arow & 7) << 4)));
    // B ([n][k] rows; x4 covers 16 n x 16 k)
    const int brow = warp_n * 64 + (lane & 7) + ((lane >> 4) << 3);
    const uint32_t offB = (uint32_t)(brow * 128 + ((((lane >> 3) & 1) * 16) ^ ((brow & 7) << 4)))
                        + B_OFF;

    float acc[2][8][4];
    #pragma unroll
    for (int a = 0; a < 2; ++a)
        #pragma unroll
        for (int f = 0; f < 8; ++f)
            #pragma unroll
            for (int c = 0; c < 4; ++c) acc[a][f][c] = 0.0f;

    // ---- prologue: stages 0..2 ----
    #pragma unroll
    for (int s = 0; s < 3; ++s) {
        const uint32_t base = tiles + s * STAGE_BYTES + rr * 128 + sw_base;
        const __half* a = gAt + s * BK;
        const __half* b = gBt + s * BK;
        #pragma unroll
        for (int i = 0; i < 4; ++i)           // A: 4 x 64 rows
            cp16(base + i * 8192, a + (size_t)i * 64 * IN_F);
        #pragma unroll
        for (int i = 0; i < 2; ++i)           // B: 2 x 64 rows
            cp16(base + B_OFF + i * 8192, b + (size_t)i * 64 * IN_F);
        CP_COMMIT();
    }

    // ---- mainloop ----
    for (int kc = 0; kc < NK; ++kc) {
        CP_WAIT(2);
        __syncthreads();

        if (kc + 3 < NK) {
            const int s = (kc + 3) & 3;
            const uint32_t base = tiles + s * STAGE_BYTES + rr * 128 + sw_base;
            const __half* a = gAt + (kc + 3) * BK;
            const __half* b = gBt + (kc + 3) * BK;
            #pragma unroll
            for (int i = 0; i < 4; ++i)
                cp16(base + i * 8192, a + (size_t)i * 64 * IN_F);
            #pragma unroll
            for (int i = 0; i < 2; ++i)
                cp16(base + B_OFF + i * 8192, b + (size_t)i * 64 * IN_F);
        }
        CP_COMMIT();

        const uint32_t stg = tiles + (kc & 3) * STAGE_BYTES;
        const uint32_t aB = stg + offA;
        const uint32_t bB = stg + offB;
        #pragma unroll
        for (int j = 0; j < 4; ++j) {         // 4 x k16 steps per BK=64
            const uint32_t jx = (uint32_t)(j << 5);
            uint32_t a0[4], a1[4], b[16];
            LDSM4(a0, aB ^ jx);                     // m 0-15
            LDSM4(a1, (aB + 2048) ^ jx);            // m 16-31
            LDSM4(&b[0],  bB ^ jx);                 // n 0-15
            LDSM4(&b[4],  (bB + 2048) ^ jx);        // n 16-31
            LDSM4(&b[8],  (bB + 4096) ^ jx);        // n 32-47
            LDSM4(&b[12], (bB + 6144) ^ jx);        // n 48-63
            #pragma unroll
            for (int f = 0; f < 8; ++f) {
                MMA_F16(acc[0][f], a0, b[2 * f], b[2 * f + 1]);
                MMA_F16(acc[1][f], a1, b[2 * f], b[2 * f + 1]);
            }
        }
    }

    // ---- epilogue: bias + cyclic activations, staged through smem ----
    CP_WAIT(0);
    __syncthreads();    // tiles no longer needed; reuse smem as output staging

    float bs0[8], bs1[8];
    #pragma unroll
    for (int f = 0; f < 8; ++f) {
        const int cb = n0 + warp_n * 64 + f * 8 + 2 * (lane & 3);
        bs0[f] = __ldg(Bv + cb);
        bs1[f] = __ldg(Bv + cb + 1);
    }

    float* eb = (float*)(smem + (tiles - sb));    // stride-136 staging, 256 rows
    const bool even = (lane & 1) == 0;

    #pragma unroll
    for (int mf = 0; mf < 2; ++mf) {
        #pragma unroll
        for (int h = 0; h < 2; ++h) {
            const int row = warp_m * 32 + mf * 16 + (lane >> 2) + h * 8;
            #pragma unroll
            for (int f = 0; f < 8; ++f) {
                float v0 = acc[mf][f][2 * h]     + bs0[f];
                float v1 = acc[mf][f][2 * h + 1] + bs1[f];
                float o0 = even ? tanh_ap(v0) : fmaxf(v0, 0.0f);            // col%4 0|2
                float o1 = even ? sin_ap(v1)
                                : fmaf(0.5f, tanh_ap(0.5f * v1), 0.5f);     // col%4 1|3
                float2 o = { o0, o1 };
                *(float2*)&eb[(size_t)row * 136 + warp_n * 64 + f * 8 + 2 * (lane & 3)] = o;
            }
        }
    }
    __syncthreads();

    // coalesced 128B streaming stores: 256 rows x 32 float4
    #pragma unroll
    for (int i = 0; i < 16; ++i) {
        const int idx = tid + i * NTHREADS;
        const int row = idx >> 5;
        const int c4  = idx & 31;
        float4 v = *(const float4*)&eb[(size_t)row * 136 + c4 * 4];
        *(float4*)(O + (size_t)(m0 + row) * OUT_F + n0 + c4 * 4) = v;
    }
}

// ---------------- launch ----------------
extern "C" void kernel_launch(void* const* d_in, const int* in_sizes, int n_in,
                              void* d_out, int out_size) {
    const float* X  = (const float*)d_in[0];
    const float* Wt = (const float*)d_in[1];
    const float* Bv = (const float*)d_in[2];
    float* O = (float*)d_out;

    cvt_x_kernel<<<(int)(((size_t)BATCH * IN_F / 8) / 256), 256>>>((const float4*)X);
    cvt_w_kernel<<<(int)(((size_t)OUT_F * IN_F / 8) / 256), 256>>>((const float4*)Wt);

    cudaFuncSetAttribute(gemm_act_kernel,
                         cudaFuncAttributeMaxDynamicSharedMemorySize, SMEM_TOTAL);
    gemm_act_kernel<<<(BATCH / BM) * (OUT_F / BN), NTHREADS, SMEM_TOTAL>>>(Bv, O);
}

// round 6
// speedup vs baseline: 2.1689x; 1.1496x over previous
#include <cuda_runtime.h>
#include <cuda_fp16.h>
#include <cstdint>

// ---------------- problem constants ----------------
#define BATCH   65536
#define IN_F    1024
#define OUT_F   1024
#define BM      128
#define BN      128
#define BK      64
#define NK      (IN_F / BK)      // 16 k-chunks
#define NTHREADS 256
#define STAGES  3

#define STAGE_BYTES 32768        // A 16KB (128x64 f16) + B 16KB (128x64 f16)
#define B_OFF       16384
#define SMEM_PAD    2048
#define SMEM_TOTAL  (SMEM_PAD + STAGES * STAGE_BYTES)   // 100352 -> 2 CTAs/SM

// fp16 copies (round-nearest). Same 10 mantissa bits as tf32; fp32 accumulate.
__device__ __half g_Xh[(size_t)BATCH * IN_F];   // 128 MB scratch
__device__ __half g_Wh[(size_t)OUT_F * IN_F];   // 2 MB scratch

// ---------------- helpers ----------------
__device__ __forceinline__ uint32_t h2_u32(__half2 h) {
    union { __half2 h; uint32_t u; } c; c.h = h; return c.u;
}
__device__ __forceinline__ uint32_t smem_u32(const void* p) {
    uint32_t a;
    asm("{ .reg .u64 t; cvta.to.shared.u64 t, %1; cvt.u32.u64 %0, t; }" : "=r"(a) : "l"(p));
    return a;
}
__device__ __forceinline__ void cp16(uint32_t s, const void* g) {
    asm volatile("cp.async.cg.shared.global [%0], [%1], 16;" :: "r"(s), "l"(g));
}
#define CP_COMMIT() asm volatile("cp.async.commit_group;" ::: "memory")
#define CP_WAIT(n)  asm volatile("cp.async.wait_group %0;" :: "n"(n) : "memory")

#define LDSM4(R, A) \
    asm volatile("ldmatrix.sync.aligned.m8n8.x4.shared.b16 {%0,%1,%2,%3}, [%4];" \
        : "=r"((R)[0]), "=r"((R)[1]), "=r"((R)[2]), "=r"((R)[3]) : "r"(A))

#define MMA_F16(D, A, B0, B1) \
    asm volatile("mma.sync.aligned.m16n8k16.row.col.f32.f16.f16.f32 " \
        "{%0,%1,%2,%3}, {%4,%5,%6,%7}, {%8,%9}, {%0,%1,%2,%3};" \
        : "+f"((D)[0]), "+f"((D)[1]), "+f"((D)[2]), "+f"((D)[3]) \
        : "r"((A)[0]), "r"((A)[1]), "r"((A)[2]), "r"((A)[3]), "r"(B0), "r"(B1))

__device__ __forceinline__ float tanh_ap(float x) {
    float y; asm("tanh.approx.f32 %0, %1;" : "=f"(y) : "f"(x)); return y;
}
__device__ __forceinline__ float sin_ap(float x) {
    float y; asm("sin.approx.f32 %0, %1;" : "=f"(y) : "f"(x)); return y;
}

// ---------------- conversion kernels (fp32 -> fp16 round-nearest) ----------------
__global__ void __launch_bounds__(256) cvt_x_kernel(const float4* __restrict__ in) {
    size_t i = (size_t)blockIdx.x * 256 + threadIdx.x;   // 8 floats each
    float4 v0 = in[2 * i], v1 = in[2 * i + 1];
    uint4 o = { h2_u32(__floats2half2_rn(v0.x, v0.y)),
                h2_u32(__floats2half2_rn(v0.z, v0.w)),
                h2_u32(__floats2half2_rn(v1.x, v1.y)),
                h2_u32(__floats2half2_rn(v1.z, v1.w)) };
    ((uint4*)g_Xh)[i] = o;
}
__global__ void __launch_bounds__(256) cvt_w_kernel(const float4* __restrict__ in) {
    size_t i = (size_t)blockIdx.x * 256 + threadIdx.x;
    float4 v0 = in[2 * i], v1 = in[2 * i + 1];
    uint4 o = { h2_u32(__floats2half2_rn(v0.x, v0.y)),
                h2_u32(__floats2half2_rn(v0.z, v0.w)),
                h2_u32(__floats2half2_rn(v1.x, v1.y)),
                h2_u32(__floats2half2_rn(v1.z, v1.w)) };
    ((uint4*)g_Wh)[i] = o;
}

// ---------------- fused fp16 GEMM (fp32 accum) + cyclic activations ----------------
__global__ void __launch_bounds__(NTHREADS, 2)
gemm_act_kernel(const float* __restrict__ Bv, float* __restrict__ O) {
    extern __shared__ char smem[];
    const uint32_t sb = smem_u32(smem);
    const uint32_t tiles = ((sb + 127) & ~127u) + SMEM_PAD - 128;

    const int tid = threadIdx.x;
    const int wid = tid >> 5;
    const int lane = tid & 31;
    const int warp_m = wid & 3;       // 0..3 -> m offset *32
    const int warp_n = wid >> 2;      // 0..1 -> n offset *64

    const int nt = blockIdx.x & 7;    // 8 N-tiles; consecutive bids share A tile in L2
    const int mt = blockIdx.x >> 3;   // 512 M-tiles
    const int m0 = mt * BM;
    const int n0 = nt * BN;

    // ---- producer addressing: row = 128B of fp16 (64 halves) ----
    const int rr = tid >> 3;                  // 0..31
    const int cc = tid & 7;                   // 16B vec
    const uint32_t sw_base = (uint32_t)((cc * 16) ^ ((rr & 7) << 4));
    const __half* gAt = g_Xh + (size_t)(m0 + rr) * IN_F + cc * 8;
    const __half* gBt = g_Wh + (size_t)(n0 + rr) * IN_F + cc * 8;

    // ---- ldmatrix per-thread offsets ----
    const int arow = warp_m * 32 + (lane & 15);
    const uint32_t offA = (uint32_t)(arow * 128 + (((lane >> 4) * 16) ^ ((arow & 7) << 4)));
    const int brow = warp_n * 64 + (lane & 7) + ((lane >> 4) << 3);
    const uint32_t offB = (uint32_t)(brow * 128 + ((((lane >> 3) & 1) * 16) ^ ((brow & 7) << 4)))
                        + B_OFF;

    float acc[2][8][4];
    #pragma unroll
    for (int a = 0; a < 2; ++a)
        #pragma unroll
        for (int f = 0; f < 8; ++f)
            #pragma unroll
            for (int c = 0; c < 4; ++c) acc[a][f][c] = 0.0f;

    // ---- prologue: stages 0..1 ----
    #pragma unroll
    for (int s = 0; s < 2; ++s) {
        const uint32_t base = tiles + s * STAGE_BYTES + rr * 128 + sw_base;
        const __half* a = gAt + s * BK;
        const __half* b = gBt + s * BK;
        #pragma unroll
        for (int i = 0; i < 4; ++i) {         // A,B: 4 x 32 rows each
            cp16(base + i * 4096,         a + (size_t)i * 32 * IN_F);
            cp16(base + B_OFF + i * 4096, b + (size_t)i * 32 * IN_F);
        }
        CP_COMMIT();
    }

    // ---- mainloop ----
    for (int kc = 0; kc < NK; ++kc) {
        CP_WAIT(1);
        __syncthreads();

        if (kc + 2 < NK) {
            const int s = (kc + 2) % STAGES;
            const uint32_t base = tiles + s * STAGE_BYTES + rr * 128 + sw_base;
            const __half* a = gAt + (kc + 2) * BK;
            const __half* b = gBt + (kc + 2) * BK;
            #pragma unroll
            for (int i = 0; i < 4; ++i) {
                cp16(base + i * 4096,         a + (size_t)i * 32 * IN_F);
                cp16(base + B_OFF + i * 4096, b + (size_t)i * 32 * IN_F);
            }
        }
        CP_COMMIT();   // one group per kc keeps the wait-count invariant

        const uint32_t stg = tiles + (kc % STAGES) * STAGE_BYTES;
        const uint32_t aB = stg + offA;
        const uint32_t bB = stg + offB;
        #pragma unroll
        for (int j = 0; j < 4; ++j) {         // 4 x k16 steps per BK=64
            const uint32_t jx = (uint32_t)(j << 5);
            uint32_t a0[4], a1[4], b[16];
            LDSM4(a0, aB ^ jx);                     // m 0-15
            LDSM4(a1, (aB + 2048) ^ jx);            // m 16-31
            LDSM4(&b[0],  bB ^ jx);                 // n 0-15
            LDSM4(&b[4],  (bB + 2048) ^ jx);        // n 16-31
            LDSM4(&b[8],  (bB + 4096) ^ jx);        // n 32-47
            LDSM4(&b[12], (bB + 6144) ^ jx);        // n 48-63
            #pragma unroll
            for (int f = 0; f < 8; ++f) {
                MMA_F16(acc[0][f], a0, b[2 * f], b[2 * f + 1]);
                MMA_F16(acc[1][f], a1, b[2 * f], b[2 * f + 1]);
            }
        }
    }

    // ---- epilogue: bias + cyclic activations, staged through smem ----
    CP_WAIT(0);
    __syncthreads();    // tiles no longer needed; reuse smem as output staging

    float bs0[8], bs1[8];
    #pragma unroll
    for (int f = 0; f < 8; ++f) {
        const int cb = n0 + warp_n * 64 + f * 8 + 2 * (lane & 3);
        bs0[f] = __ldg(Bv + cb);
        bs1[f] = __ldg(Bv + cb + 1);
    }

    float* eb = (float*)(smem + (tiles - sb));    // stride-136 staging, 128 rows (69.6KB)
    const bool even = (lane & 1) == 0;

    #pragma unroll
    for (int mf = 0; mf < 2; ++mf) {
        #pragma unroll
        for (int h = 0; h < 2; ++h) {
            const int row = warp_m * 32 + mf * 16 + (lane >> 2) + h * 8;
            #pragma unroll
            for (int f = 0; f < 8; ++f) {
                float v0 = acc[mf][f][2 * h]     + bs0[f];
                float v1 = acc[mf][f][2 * h + 1] + bs1[f];
                float o0 = even ? tanh_ap(v0) : fmaxf(v0, 0.0f);            // col%4 0|2
                float o1 = even ? sin_ap(v1)
                                : fmaf(0.5f, tanh_ap(0.5f * v1), 0.5f);     // col%4 1|3
                float2 o = { o0, o1 };
                *(float2*)&eb[(size_t)row * 136 + warp_n * 64 + f * 8 + 2 * (lane & 3)] = o;
            }
        }
    }
    __syncthreads();

    // coalesced 128B streaming stores: 128 rows x 32 float4
    #pragma unroll
    for (int i = 0; i < 16; ++i) {
        const int idx = tid + i * NTHREADS;
        const int row = idx >> 5;
        const int c4  = idx & 31;
        float4 v = *(const float4*)&eb[(size_t)row * 136 + c4 * 4];
        *(float4*)(O + (size_t)(m0 + row) * OUT_F + n0 + c4 * 4) = v;
    }
}

// ---------------- launch ----------------
extern "C" void kernel_launch(void* const* d_in, const int* in_sizes, int n_in,
                              void* d_out, int out_size) {
    const float* X  = (const float*)d_in[0];
    const float* Wt = (const float*)d_in[1];
    const float* Bv = (const float*)d_in[2];
    float* O = (float*)d_out;

    cvt_x_kernel<<<(int)(((size_t)BATCH * IN_F / 8) / 256), 256>>>((const float4*)X);
    cvt_w_kernel<<<(int)(((size_t)OUT_F * IN_F / 8) / 256), 256>>>((const float4*)Wt);

    cudaFuncSetAttribute(gemm_act_kernel,
                         cudaFuncAttributeMaxDynamicSharedMemorySize, SMEM_TOTAL);
    gemm_act_kernel<<<(BATCH / BM) * (OUT_F / BN), NTHREADS, SMEM_TOTAL>>>(Bv, O);
}